// round 11
// baseline (speedup 1.0000x reference)
#include <cuda_runtime.h>
#include <cuda_bf16.h>
#include <math.h>
#include <stdint.h>

// Problem dims
#define Bn 512
#define Tn 512
#define In 256
#define Hn 250

// ---------------- helpers ----------------------------------------------------
__device__ __forceinline__ uint32_t smem_u32(const void* p) {
    uint32_t a;
    asm("{ .reg .u64 t; cvta.to.shared.u64 t, %1; cvt.u32.u64 %0, t; }"
        : "=r"(a) : "l"(p));
    return a;
}
__device__ __forceinline__ uint32_t bf16x2_rn(float lo, float hi) {
    uint32_t r;
    asm("cvt.rn.bf16x2.f32 %0, %1, %2;" : "=r"(r) : "f"(hi), "f"(lo));
    return r;
}
__device__ __forceinline__ void ldsm4(uint32_t* r, uint32_t addr) {
    asm volatile("ldmatrix.sync.aligned.m8n8.x4.shared.b16 {%0,%1,%2,%3}, [%4];"
                 : "=r"(r[0]), "=r"(r[1]), "=r"(r[2]), "=r"(r[3]) : "r"(addr));
}
__device__ __forceinline__ void mma16816(float* c, const uint32_t* a,
                                         const uint32_t* b) {
    asm volatile(
        "mma.sync.aligned.m16n8k16.row.col.f32.bf16.bf16.f32 "
        "{%0,%1,%2,%3}, {%4,%5,%6,%7}, {%8,%9}, {%0,%1,%2,%3};"
        : "+f"(c[0]), "+f"(c[1]), "+f"(c[2]), "+f"(c[3])
        : "r"(a[0]), "r"(a[1]), "r"(a[2]), "r"(a[3]), "r"(b[0]), "r"(b[1]));
}
#define CPASYNC16(dst, src) \
    asm volatile("cp.async.cg.shared.global [%0], [%1], 16;" \
                 :: "r"(dst), "l"(src))
#define CP_COMMIT() asm volatile("cp.async.commit_group;" ::: "memory")
#define CP_WAIT1()  asm volatile("cp.async.wait_group 1;" ::: "memory")
#define CLUSTER_ARRIVE() asm volatile("barrier.cluster.arrive.aligned;" ::: "memory")
#define CLUSTER_WAIT()   asm volatile("barrier.cluster.wait.aligned;" ::: "memory")

__device__ __forceinline__ void sts_u32(uint32_t addr, uint32_t v) {
    asm volatile("st.shared.u32 [%0], %1;" :: "r"(addr), "r"(v));
}
__device__ __forceinline__ void sts_cluster_u32(uint32_t addr, uint32_t v) {
    asm volatile("st.shared::cluster.u32 [%0], %1;" :: "r"(addr), "r"(v));
}
__device__ __forceinline__ void mbar_init2(uint32_t a) {
    asm volatile("mbarrier.init.shared.b64 [%0], 2;" :: "r"(a) : "memory");
}
__device__ __forceinline__ void mbar_arrive_local(uint32_t a) {
    asm volatile("mbarrier.arrive.release.cluster.shared::cta.b64 _, [%0];"
                 :: "r"(a) : "memory");
}
__device__ __forceinline__ void mbar_arrive_remote(uint32_t a) {
    asm volatile("mbarrier.arrive.release.cluster.shared::cluster.b64 _, [%0];"
                 :: "r"(a) : "memory");
}
__device__ __forceinline__ void mbar_wait_acq(uint32_t a, uint32_t parity) {
    asm volatile(
        "{\n\t.reg .pred P;\n\t"
        "WLP_%=:\n\t"
        "mbarrier.try_wait.parity.acquire.cluster.shared::cta.b64 P, [%0], %1;\n\t"
        "@P bra.uni WDN_%=;\n\t"
        "bra.uni WLP_%=;\n\t"
        "WDN_%=:\n\t}"
        :: "r"(a), "r"(parity) : "memory");
}

// fast tanh: 1 - 2/(e^{2x}+1), MUFU-based (abs err ~1e-6)
__device__ __forceinline__ float tanh_fast(float x) {
    float e;
    asm("ex2.approx.f32 %0, %1;" : "=f"(e) : "f"(x * 2.8853900817779268f));
    float r;
    asm("rcp.approx.f32 %0, %1;" : "=f"(r) : "f"(e + 1.0f));
    return fmaf(-2.0f, r, 1.0f);
}

// ---------------- scratch ----------------------------------------------------
__device__ unsigned short g_WxH[256 * 256];             // Wx hi bf16 [n][k]
__device__ unsigned short g_WxL[256 * 256];             // Wx lo bf16 [n][k]
__device__ unsigned short g_WhH[256 * 256];             // Wh hi bf16 [n][k] padded
__device__ unsigned short g_WhL[256 * 256];             // Wh lo bf16 [n][k] padded
// interleaved split x: per 8-element group: 16 B hi then 16 B lo (268 MB)
__device__ uint4 g_X2[(size_t)Bn * Tn * In / 8 * 2];

__global__ void prep_wx_kernel(const float* __restrict__ Wx) {
    int i = blockIdx.x * blockDim.x + threadIdx.x;   // 256*256
    int r = i >> 8;
    int k = i & 255;
    float w = (r < Hn) ? Wx[r * In + k] : 0.0f;
    uint32_t wb = __float_as_uint(w);
    float hif = __uint_as_float(wb & 0xFFFF0000u);
    g_WxH[i] = (unsigned short)(wb >> 16);
    g_WxL[i] = __bfloat16_as_ushort(__float2bfloat16(w - hif));
}

__global__ void prep_wh_kernel(const float* __restrict__ Wh) {
    int i = blockIdx.x * blockDim.x + threadIdx.x;   // 256*256
    int r = i >> 8;
    int k = i & 255;
    float w = (r < Hn && k < Hn) ? Wh[r * Hn + k] : 0.0f;
    uint32_t wb = __float_as_uint(w);
    float hif = __uint_as_float(wb & 0xFFFF0000u);
    g_WhH[i] = (unsigned short)(wb >> 16);
    g_WhL[i] = __bfloat16_as_ushort(__float2bfloat16(w - hif));
}

// split x -> interleaved hi/lo groups; 32 B contiguous read+write per thread
__global__ void prep_x_kernel(const float* __restrict__ X) {
    size_t i = (size_t)blockIdx.x * blockDim.x + threadIdx.x;   // 8-elem group
    float4 v0 = ((const float4*)X)[2 * i];
    float4 v1 = ((const float4*)X)[2 * i + 1];
    uint4 hp, lp;
    hp.x = __byte_perm(__float_as_uint(v0.x), __float_as_uint(v0.y), 0x7632);
    hp.y = __byte_perm(__float_as_uint(v0.z), __float_as_uint(v0.w), 0x7632);
    hp.z = __byte_perm(__float_as_uint(v1.x), __float_as_uint(v1.y), 0x7632);
    hp.w = __byte_perm(__float_as_uint(v1.z), __float_as_uint(v1.w), 0x7632);
    #define REM(f) ((f) - __uint_as_float(__float_as_uint(f) & 0xFFFF0000u))
    lp.x = bf16x2_rn(REM(v0.x), REM(v0.y));
    lp.y = bf16x2_rn(REM(v0.z), REM(v0.w));
    lp.z = bf16x2_rn(REM(v1.x), REM(v1.y));
    lp.w = bf16x2_rn(REM(v1.z), REM(v1.w));
    #undef REM
    g_X2[2 * i]     = hp;
    g_X2[2 * i + 1] = lp;
}

// ---------------- Phase 1: xproj via HMMA bf16-split GEMM (R8 proven) --------
#define SBH   80
#define RBUF  (128 * SBH)
#define STG   (4 * RBUF)
#define SMTOT (2 * STG)

__global__ __launch_bounds__(256, 2)
void gemm_xproj_hmma(float* __restrict__ out) {
    extern __shared__ __align__(16) char smc[];
    const uint32_t smb = smem_u32(smc);

    const int tid  = threadIdx.x;
    const int lane = tid & 31;
    const int warp = tid >> 5;
    const int wm = warp >> 1;
    const int wn = warp & 1;
    const size_t m0 = (size_t)blockIdx.x * 128;
    const int n0c = blockIdx.y * 128;

    const int r0 = tid >> 1, c40 = (tid & 1) * 2;
    const char* gx  = (const char*)g_X2;
    const char* gwh = (const char*)g_WxH;
    const char* gwl = (const char*)g_WxL;

    float acc[2][8][4];
    #pragma unroll
    for (int mi = 0; mi < 2; mi++)
        #pragma unroll
        for (int ni = 0; ni < 8; ni++)
            #pragma unroll
            for (int q = 0; q < 4; q++) acc[mi][ni][q] = 0.0f;

    const uint32_t aoff = (uint32_t)((wm * 32 + (lane & 15)) * SBH + (lane >> 4) * 16);
    const uint32_t boff = (uint32_t)((wn * 64 + (lane >> 4) * 8 + (lane & 7)) * SBH +
                                     ((lane >> 3) & 1) * 16);

    auto load_stage = [&](int s, int k0) {
        uint32_t sb = smb + s * STG;
        #pragma unroll
        for (int i = 0; i < 2; i++) {
            int c4 = c40 + i;
            uint32_t d = sb + r0 * SBH + c4 * 16;
            size_t ag = ((m0 + r0) * In + k0 + c4 * 8) >> 3;   // 8-elem group
            size_t bo = (((size_t)(n0c + r0)) * In + k0 + c4 * 8) * 2;
            CPASYNC16(d,            gx + ag * 32);
            CPASYNC16(d + RBUF,     gx + ag * 32 + 16);
            CPASYNC16(d + 2 * RBUF, gwh + bo);
            CPASYNC16(d + 3 * RBUF, gwl + bo);
        }
    };

    load_stage(0, 0);  CP_COMMIT();
    load_stage(1, 32); CP_COMMIT();

    for (int c = 0; c < 8; c++) {
        CP_WAIT1();
        __syncthreads();

        const uint32_t sb = smb + (c & 1) * STG;
        const uint32_t a_h = sb + aoff,            a_l = sb + RBUF + aoff;
        const uint32_t b_h = sb + 2 * RBUF + boff, b_l = sb + 3 * RBUF + boff;

        #pragma unroll
        for (int ks = 0; ks < 2; ks++) {
            const uint32_t ko = ks * 32;
            uint32_t ahf[2][4], alf[2][4], bf[8][2];
            ldsm4(ahf[0], a_h + ko);
            ldsm4(ahf[1], a_h + 16 * SBH + ko);
            ldsm4(alf[0], a_l + ko);
            ldsm4(alf[1], a_l + 16 * SBH + ko);
            #pragma unroll
            for (int jp = 0; jp < 4; jp++) {
                uint32_t r[4];
                ldsm4(r, b_h + jp * 16 * SBH + ko);
                bf[jp * 2][0] = r[0]; bf[jp * 2][1] = r[1];
                bf[jp * 2 + 1][0] = r[2]; bf[jp * 2 + 1][1] = r[3];
            }
            #pragma unroll
            for (int mi = 0; mi < 2; mi++)
                #pragma unroll
                for (int ni = 0; ni < 8; ni++) {
                    mma16816(acc[mi][ni], ahf[mi], bf[ni]);
                    mma16816(acc[mi][ni], alf[mi], bf[ni]);
                }
            #pragma unroll
            for (int jp = 0; jp < 4; jp++) {
                uint32_t r[4];
                ldsm4(r, b_l + jp * 16 * SBH + ko);
                bf[jp * 2][0] = r[0]; bf[jp * 2][1] = r[1];
                bf[jp * 2 + 1][0] = r[2]; bf[jp * 2 + 1][1] = r[3];
            }
            #pragma unroll
            for (int mi = 0; mi < 2; mi++)
                #pragma unroll
                for (int ni = 0; ni < 8; ni++)
                    mma16816(acc[mi][ni], ahf[mi], bf[ni]);
        }
        __syncthreads();

        if (c + 2 < 8) load_stage(c & 1, (c + 2) * 32);
        CP_COMMIT();
    }

    const int g = lane >> 2, tg = lane & 3;
    #pragma unroll
    for (int mi = 0; mi < 2; mi++) {
        size_t r = m0 + wm * 32 + mi * 16 + g;
        #pragma unroll
        for (int ni = 0; ni < 8; ni++) {
            int col = n0c + wn * 64 + ni * 8 + tg * 2;
            if (col < Hn) {
                *(float2*)(out + r * Hn + col) =
                    make_float2(acc[mi][ni][0], acc[mi][ni][1]);
                *(float2*)(out + (r + 8) * Hn + col) =
                    make_float2(acc[mi][ni][2], acc[mi][ni][3]);
            }
        }
    }
}

// ---------------- Phase 2: HMMA recurrent scan (2-CTA cluster, mbarrier) -----
// Bytes 0..15 of smem: two 2-count mbarriers (one per h ping-pong buffer).
#define S_WHH  16
#define S_WHL  (S_WHH + 128 * 528)          // 67584 each
#define S_HB   (S_WHL + 128 * 528)          // 135184
#define HB_SZ  16896                        // (hi + lo) [16][264] bf16
#define HB_LO  8448
#define S_TOT  (S_HB + 2 * HB_SZ)           // 168976 B

__global__ __launch_bounds__(256, 1) __cluster_dims__(2, 1, 1)
void rnn_scan_mma(const float* __restrict__ h0,
                  const float* __restrict__ bh,
                  float* out) {
    extern __shared__ __align__(16) char smc[];
    const uint32_t smb = smem_u32(smc);
    const int tid  = threadIdx.x;
    const int lane = tid & 31;
    const int warp = tid >> 5;
    uint32_t rank;
    asm("mov.u32 %0, %%cluster_ctarank;" : "=r"(rank));
    const int b0 = (blockIdx.x >> 1) * 16;       // batch base
    const int nh = rank * 128;                   // owned n-half base

    // mbarriers (2 arrivals each: own rep + peer rep)
    if (tid == 0) { mbar_init2(smb); mbar_init2(smb + 8); }

    // ---- load Wh half (hi/lo) into smem, row stride 264 bf16 (=528 B)
    #pragma unroll
    for (int it = 0; it < 16; it++) {
        int u = tid + 256 * it;                  // 4096 uint4 total
        int n = u >> 5, kk = u & 31;
        uint32_t off = (uint32_t)(n * 528 + kk * 16);
        *(uint4*)(smc + S_WHH + off) = ((const uint4*)g_WhH)[(size_t)(nh + n) * 32 + kk];
        *(uint4*)(smc + S_WHL + off) = ((const uint4*)g_WhL)[(size_t)(nh + n) * 32 + kk];
    }
    // ---- init h buffer 0 with full h0 (both halves), bf16 hi/lo split
    for (int idx = tid; idx < 16 * 264; idx += 256) {
        int m = idx / 264, c = idx - m * 264;
        float v = (c < Hn) ? h0[(size_t)(b0 + m) * Hn + c] : 0.0f;
        uint32_t bv = __float_as_uint(v);
        *(unsigned short*)(smc + S_HB + m * 528 + c * 2) = (unsigned short)(bv >> 16);
        float r = v - __uint_as_float(bv & 0xFFFF0000u);
        *(unsigned short*)(smc + S_HB + HB_LO + m * 528 + c * 2) =
            __bfloat16_as_ushort(__float2bfloat16(r));
    }
    __syncthreads();
    // one-time cluster barrier: both CTAs' mbarrier inits visible before any
    // remote arrive can land
    CLUSTER_ARRIVE();
    CLUSTER_WAIT();

    // ---- Wh fragments -> registers (persistent across all steps)
    uint32_t bhf[16][4], blf[16][4];
    const uint32_t boff = (uint32_t)((16 * warp + ((lane >> 4) << 3) + (lane & 7)) * 528 +
                                     ((lane >> 3) & 1) * 16);
    #pragma unroll
    for (int ks = 0; ks < 16; ks++) {
        ldsm4(bhf[ks], smb + S_WHH + boff + ks * 32);
        ldsm4(blf[ks], smb + S_WHL + boff + ks * 32);
    }

    // ---- geometry + bias
    const int g = lane >> 2, tg = lane & 3;
    const int colA = nh + 16 * warp + 2 * tg;    // always < 250
    const int colB = colA + 8;                   // may exceed 249 (rank 1, warp 7)
    const float2 biasA = *(const float2*)(bh + colA);
    const float2 biasB = (colB < Hn) ? *(const float2*)(bh + colB) : make_float2(0.f, 0.f);
    const uint32_t aoffs = (uint32_t)((lane & 15) * 528 + (lane >> 4) * 16);

    uint32_t peer_smb;
    asm("mapa.shared::cluster.u32 %0, %1, %2;"
        : "=r"(peer_smb) : "r"(smb), "r"(rank ^ 1));
    const uint32_t peer_hb = peer_smb + S_HB;

    // preload xp for t = 0
    float2 xpA0, xpA8, xpB0, xpB8;
    {
        const size_t o0 = ((size_t)(b0 + g) * Tn + 0) * Hn;
        const size_t o8 = ((size_t)(b0 + g + 8) * Tn + 0) * Hn;
        xpA0 = *(const float2*)(out + o0 + colA);
        xpA8 = *(const float2*)(out + o8 + colA);
        xpB0 = (colB < Hn) ? *(const float2*)(out + o0 + colB) : make_float2(0.f, 0.f);
        xpB8 = (colB < Hn) ? *(const float2*)(out + o8 + colB) : make_float2(0.f, 0.f);
    }

    for (int t = 0; t < Tn; t++) {
        if (t > 0) {
            mbar_wait_acq(smb + 8u * (uint32_t)(t & 1),
                          (uint32_t)(((t - 1) >> 1) & 1));
        }

        const uint32_t hbR = smb + S_HB + (uint32_t)(t & 1) * HB_SZ;

        float acc0[4] = {0.f, 0.f, 0.f, 0.f};
        float acc1[4] = {0.f, 0.f, 0.f, 0.f};

        #pragma unroll
        for (int ks = 0; ks < 16; ks++) {
            uint32_t ah[4], al[4];
            ldsm4(ah, hbR + aoffs + ks * 32);
            ldsm4(al, hbR + HB_LO + aoffs + ks * 32);
            mma16816(acc0, ah, bhf[ks]);
            mma16816(acc1, ah, bhf[ks] + 2);
            mma16816(acc0, ah, blf[ks]);
            mma16816(acc1, ah, blf[ks] + 2);
            mma16816(acc0, al, bhf[ks]);
            mma16816(acc1, al, bhf[ks] + 2);
        }

        // ---- epilogue: tanh, write out, split h -> own + peer next buffer
        const uint32_t hbW  = smb + S_HB + (uint32_t)((t + 1) & 1) * HB_SZ;
        const uint32_t phbW = peer_hb + (uint32_t)((t + 1) & 1) * HB_SZ;
        const size_t orow0 = ((size_t)(b0 + g) * Tn + t) * Hn;
        const size_t orow8 = ((size_t)(b0 + g + 8) * Tn + t) * Hn;

        float vA0 = tanh_fast(acc0[0] + xpA0.x + biasA.x);
        float vA1 = tanh_fast(acc0[1] + xpA0.y + biasA.y);
        float vA2 = tanh_fast(acc0[2] + xpA8.x + biasA.x);
        float vA3 = tanh_fast(acc0[3] + xpA8.y + biasA.y);
        *(float2*)(out + orow0 + colA) = make_float2(vA0, vA1);
        *(float2*)(out + orow8 + colA) = make_float2(vA2, vA3);

        float vB0 = 0.f, vB1 = 0.f, vB2 = 0.f, vB3 = 0.f;
        if (colB < Hn) {
            vB0 = tanh_fast(acc1[0] + xpB0.x + biasB.x);
            vB1 = tanh_fast(acc1[1] + xpB0.y + biasB.y);
            vB2 = tanh_fast(acc1[2] + xpB8.x + biasB.x);
            vB3 = tanh_fast(acc1[3] + xpB8.y + biasB.y);
            *(float2*)(out + orow0 + colB) = make_float2(vB0, vB1);
            *(float2*)(out + orow8 + colB) = make_float2(vB2, vB3);
        }

        #define STORE_H(row, col, v0, v1) do {                                   \
            uint32_t hp = __byte_perm(__float_as_uint(v0), __float_as_uint(v1),  \
                                      0x7632);                                   \
            float r0_ = (v0) - __uint_as_float(__float_as_uint(v0) & 0xFFFF0000u);\
            float r1_ = (v1) - __uint_as_float(__float_as_uint(v1) & 0xFFFF0000u);\
            uint32_t lp = bf16x2_rn(r0_, r1_);                                   \
            uint32_t off_ = (uint32_t)((row) * 528 + (col) * 2);                 \
            sts_u32(hbW + off_, hp);                                             \
            sts_u32(hbW + HB_LO + off_, lp);                                     \
            sts_cluster_u32(phbW + off_, hp);                                    \
            sts_cluster_u32(phbW + HB_LO + off_, lp);                            \
        } while (0)

        STORE_H(g,     colA, vA0, vA1);
        STORE_H(g + 8, colA, vA2, vA3);
        STORE_H(g,     colB, vB0, vB1);
        STORE_H(g + 8, colB, vB2, vB3);
        #undef STORE_H

        __syncthreads();
        if (tid == 0) {
            uint32_t b = (uint32_t)((t + 1) & 1);
            mbar_arrive_local(smb + 8u * b);
            mbar_arrive_remote(peer_smb + 8u * b);
        }

        // prefetch xp for t+1 (hides behind next wait + mma)
        if (t + 1 < Tn) {
            const size_t n0 = ((size_t)(b0 + g) * Tn + (t + 1)) * Hn;
            const size_t n8 = ((size_t)(b0 + g + 8) * Tn + (t + 1)) * Hn;
            xpA0 = *(const float2*)(out + n0 + colA);
            xpA8 = *(const float2*)(out + n8 + colA);
            if (colB < Hn) {
                xpB0 = *(const float2*)(out + n0 + colB);
                xpB8 = *(const float2*)(out + n8 + colB);
            }
        }
    }
    // no CTA exits while peer may still store into its smem
    CLUSTER_ARRIVE();
    CLUSTER_WAIT();
}

// ---------------- launch ------------------------------------------------------
extern "C" void kernel_launch(void* const* d_in, const int* in_sizes, int n_in,
                              void* d_out, int out_size) {
    const float* x  = (const float*)d_in[0];   // [512,512,256]
    const float* h0 = (const float*)d_in[1];   // [512,250]
    const float* Wx = (const float*)d_in[2];   // [250,256]
    const float* Wh = (const float*)d_in[3];   // [250,250]
    const float* bh = (const float*)d_in[4];   // [250]
    float* out = (float*)d_out;                // [512,512,250]

    // 1) weight + input prep
    prep_wx_kernel<<<256, 256>>>(Wx);
    prep_wh_kernel<<<256, 256>>>(Wh);
    prep_x_kernel<<<(int)(((size_t)Bn * Tn * In / 8) / 256), 256>>>(x);

    // 2) xproj HMMA GEMM (R8 shape: occ 2, grid.y = 2)
    cudaFuncSetAttribute(gemm_xproj_hmma,
                         cudaFuncAttributeMaxDynamicSharedMemorySize, SMTOT);
    dim3 grid((Bn * Tn) / 128, 2);
    gemm_xproj_hmma<<<grid, 256, SMTOT>>>(out);

    // 3) HMMA recurrent scan (clustered, mbarrier-paced, in-place over d_out)
    cudaFuncSetAttribute(rnn_scan_mma,
                         cudaFuncAttributeMaxDynamicSharedMemorySize, S_TOT);
    rnn_scan_mma<<<Bn / 8, 256, S_TOT>>>(h0, bh, out);
}

// round 12
// speedup vs baseline: 1.4909x; 1.4909x over previous
#include <cuda_runtime.h>
#include <cuda_bf16.h>
#include <math.h>
#include <stdint.h>

// Problem dims
#define Bn 512
#define Tn 512
#define In 256
#define Hn 250

// ---------------- helpers ----------------------------------------------------
__device__ __forceinline__ uint32_t smem_u32(const void* p) {
    uint32_t a;
    asm("{ .reg .u64 t; cvta.to.shared.u64 t, %1; cvt.u32.u64 %0, t; }"
        : "=r"(a) : "l"(p));
    return a;
}
__device__ __forceinline__ uint32_t bf16x2_rn(float lo, float hi) {
    uint32_t r;
    asm("cvt.rn.bf16x2.f32 %0, %1, %2;" : "=r"(r) : "f"(hi), "f"(lo));
    return r;
}
__device__ __forceinline__ void ldsm4(uint32_t* r, uint32_t addr) {
    asm volatile("ldmatrix.sync.aligned.m8n8.x4.shared.b16 {%0,%1,%2,%3}, [%4];"
                 : "=r"(r[0]), "=r"(r[1]), "=r"(r[2]), "=r"(r[3]) : "r"(addr));
}
__device__ __forceinline__ void mma16816(float* c, const uint32_t* a,
                                         const uint32_t* b) {
    asm volatile(
        "mma.sync.aligned.m16n8k16.row.col.f32.bf16.bf16.f32 "
        "{%0,%1,%2,%3}, {%4,%5,%6,%7}, {%8,%9}, {%0,%1,%2,%3};"
        : "+f"(c[0]), "+f"(c[1]), "+f"(c[2]), "+f"(c[3])
        : "r"(a[0]), "r"(a[1]), "r"(a[2]), "r"(a[3]), "r"(b[0]), "r"(b[1]));
}
#define CPASYNC16(dst, src) \
    asm volatile("cp.async.cg.shared.global [%0], [%1], 16;" \
                 :: "r"(dst), "l"(src))
#define CP_COMMIT() asm volatile("cp.async.commit_group;" ::: "memory")
#define CP_WAIT1()  asm volatile("cp.async.wait_group 1;" ::: "memory")
#define CLUSTER_ARRIVE() asm volatile("barrier.cluster.arrive.aligned;" ::: "memory")
#define CLUSTER_WAIT()   asm volatile("barrier.cluster.wait.aligned;" ::: "memory")

__device__ __forceinline__ void sts_u32(uint32_t addr, uint32_t v) {
    asm volatile("st.shared.u32 [%0], %1;" :: "r"(addr), "r"(v));
}
__device__ __forceinline__ void sts_cluster_u32(uint32_t addr, uint32_t v) {
    asm volatile("st.shared::cluster.u32 [%0], %1;" :: "r"(addr), "r"(v));
}

// fast tanh: 1 - 2/(e^{2x}+1), MUFU-based (abs err ~1e-6)
__device__ __forceinline__ float tanh_fast(float x) {
    float e;
    asm("ex2.approx.f32 %0, %1;" : "=f"(e) : "f"(x * 2.8853900817779268f));
    float r;
    asm("rcp.approx.f32 %0, %1;" : "=f"(r) : "f"(e + 1.0f));
    return fmaf(-2.0f, r, 1.0f);
}

// ---------------- scratch ----------------------------------------------------
__device__ unsigned short g_WxH[256 * 256];             // Wx hi bf16 [n][k]
__device__ unsigned short g_WxL[256 * 256];             // Wx lo bf16 [n][k]
__device__ unsigned short g_WhH[256 * 256];             // Wh hi bf16 [n][k] padded
__device__ unsigned short g_WhL[256 * 256];             // Wh lo bf16 [n][k] padded
__device__ unsigned short g_XH[(size_t)Bn * Tn * In];   // x hi bf16 (128 MB)
__device__ unsigned short g_XL[(size_t)Bn * Tn * In];   // x lo bf16 (128 MB)

__global__ void prep_wx_kernel(const float* __restrict__ Wx) {
    int i = blockIdx.x * blockDim.x + threadIdx.x;   // 256*256
    int r = i >> 8;
    int k = i & 255;
    float w = (r < Hn) ? Wx[r * In + k] : 0.0f;
    uint32_t wb = __float_as_uint(w);
    float hif = __uint_as_float(wb & 0xFFFF0000u);
    g_WxH[i] = (unsigned short)(wb >> 16);
    g_WxL[i] = __bfloat16_as_ushort(__float2bfloat16(w - hif));
}

__global__ void prep_wh_kernel(const float* __restrict__ Wh) {
    int i = blockIdx.x * blockDim.x + threadIdx.x;   // 256*256
    int r = i >> 8;
    int k = i & 255;
    float w = (r < Hn && k < Hn) ? Wh[r * Hn + k] : 0.0f;
    uint32_t wb = __float_as_uint(w);
    float hif = __uint_as_float(wb & 0xFFFF0000u);
    g_WhH[i] = (unsigned short)(wb >> 16);
    g_WhL[i] = __bfloat16_as_ushort(__float2bfloat16(w - hif));
}

__global__ void prep_x_kernel(const float* __restrict__ X) {
    size_t i = (size_t)blockIdx.x * blockDim.x + threadIdx.x;   // float4 id
    float4 v = ((const float4*)X)[i];
    uint2 hp, lp;
    hp.x = __byte_perm(__float_as_uint(v.x), __float_as_uint(v.y), 0x7632);
    hp.y = __byte_perm(__float_as_uint(v.z), __float_as_uint(v.w), 0x7632);
    #define REM(f) ((f) - __uint_as_float(__float_as_uint(f) & 0xFFFF0000u))
    lp.x = bf16x2_rn(REM(v.x), REM(v.y));
    lp.y = bf16x2_rn(REM(v.z), REM(v.w));
    #undef REM
    ((uint2*)g_XH)[i] = hp;
    ((uint2*)g_XL)[i] = lp;
}

// ---------------- Phase 1: xproj via HMMA bf16-split GEMM (R8/R10 proven) ----
#define SBH   80
#define RBUF  (128 * SBH)
#define STG   (4 * RBUF)
#define SMTOT (2 * STG)

__global__ __launch_bounds__(256, 2)
void gemm_xproj_hmma(float* __restrict__ out) {
    extern __shared__ __align__(16) char smc[];
    const uint32_t smb = smem_u32(smc);

    const int tid  = threadIdx.x;
    const int lane = tid & 31;
    const int warp = tid >> 5;
    const int wm = warp >> 1;
    const int wn = warp & 1;
    const size_t m0 = (size_t)blockIdx.x * 128;
    const int n0c = blockIdx.y * 128;

    const int r0 = tid >> 1, c40 = (tid & 1) * 2;
    const char* gxh = (const char*)g_XH;
    const char* gxl = (const char*)g_XL;
    const char* gwh = (const char*)g_WxH;
    const char* gwl = (const char*)g_WxL;

    float acc[2][8][4];
    #pragma unroll
    for (int mi = 0; mi < 2; mi++)
        #pragma unroll
        for (int ni = 0; ni < 8; ni++)
            #pragma unroll
            for (int q = 0; q < 4; q++) acc[mi][ni][q] = 0.0f;

    const uint32_t aoff = (uint32_t)((wm * 32 + (lane & 15)) * SBH + (lane >> 4) * 16);
    const uint32_t boff = (uint32_t)((wn * 64 + (lane >> 4) * 8 + (lane & 7)) * SBH +
                                     ((lane >> 3) & 1) * 16);

    auto load_stage = [&](int s, int k0) {
        uint32_t sb = smb + s * STG;
        #pragma unroll
        for (int i = 0; i < 2; i++) {
            int c4 = c40 + i;
            uint32_t d = sb + r0 * SBH + c4 * 16;
            size_t ao = ((m0 + r0) * In + k0 + c4 * 8) * 2;
            size_t bo = (((size_t)(n0c + r0)) * In + k0 + c4 * 8) * 2;
            CPASYNC16(d,            gxh + ao);
            CPASYNC16(d + RBUF,     gxl + ao);
            CPASYNC16(d + 2 * RBUF, gwh + bo);
            CPASYNC16(d + 3 * RBUF, gwl + bo);
        }
    };

    load_stage(0, 0);  CP_COMMIT();
    load_stage(1, 32); CP_COMMIT();

    for (int c = 0; c < 8; c++) {
        CP_WAIT1();
        __syncthreads();

        const uint32_t sb = smb + (c & 1) * STG;
        const uint32_t a_h = sb + aoff,            a_l = sb + RBUF + aoff;
        const uint32_t b_h = sb + 2 * RBUF + boff, b_l = sb + 3 * RBUF + boff;

        #pragma unroll
        for (int ks = 0; ks < 2; ks++) {
            const uint32_t ko = ks * 32;
            uint32_t ahf[2][4], alf[2][4], bf[8][2];
            ldsm4(ahf[0], a_h + ko);
            ldsm4(ahf[1], a_h + 16 * SBH + ko);
            ldsm4(alf[0], a_l + ko);
            ldsm4(alf[1], a_l + 16 * SBH + ko);
            #pragma unroll
            for (int jp = 0; jp < 4; jp++) {
                uint32_t r[4];
                ldsm4(r, b_h + jp * 16 * SBH + ko);
                bf[jp * 2][0] = r[0]; bf[jp * 2][1] = r[1];
                bf[jp * 2 + 1][0] = r[2]; bf[jp * 2 + 1][1] = r[3];
            }
            #pragma unroll
            for (int mi = 0; mi < 2; mi++)
                #pragma unroll
                for (int ni = 0; ni < 8; ni++) {
                    mma16816(acc[mi][ni], ahf[mi], bf[ni]);
                    mma16816(acc[mi][ni], alf[mi], bf[ni]);
                }
            #pragma unroll
            for (int jp = 0; jp < 4; jp++) {
                uint32_t r[4];
                ldsm4(r, b_l + jp * 16 * SBH + ko);
                bf[jp * 2][0] = r[0]; bf[jp * 2][1] = r[1];
                bf[jp * 2 + 1][0] = r[2]; bf[jp * 2 + 1][1] = r[3];
            }
            #pragma unroll
            for (int mi = 0; mi < 2; mi++)
                #pragma unroll
                for (int ni = 0; ni < 8; ni++)
                    mma16816(acc[mi][ni], ahf[mi], bf[ni]);
        }
        __syncthreads();

        if (c + 2 < 8) load_stage(c & 1, (c + 2) * 32);
        CP_COMMIT();
    }

    const int g = lane >> 2, tg = lane & 3;
    #pragma unroll
    for (int mi = 0; mi < 2; mi++) {
        size_t r = m0 + wm * 32 + mi * 16 + g;
        #pragma unroll
        for (int ni = 0; ni < 8; ni++) {
            int col = n0c + wn * 64 + ni * 8 + tg * 2;
            if (col < Hn) {
                *(float2*)(out + r * Hn + col) =
                    make_float2(acc[mi][ni][0], acc[mi][ni][1]);
                *(float2*)(out + (r + 8) * Hn + col) =
                    make_float2(acc[mi][ni][2], acc[mi][ni][3]);
            }
        }
    }
}

// ---------------- Phase 2: HMMA recurrent scan (2-CTA cluster, R10 proto) ----
#define S_WHH  16
#define S_WHL  (S_WHH + 128 * 528)          // 67584 each
#define S_HB   (S_WHL + 128 * 528)          // 135184
#define HB_SZ  16896                        // (hi + lo) [16][264] bf16
#define HB_LO  8448
#define S_TOT  (S_HB + 2 * HB_SZ)           // 168976 B

__global__ __launch_bounds__(256, 1) __cluster_dims__(2, 1, 1)
void rnn_scan_mma(const float* __restrict__ h0,
                  const float* __restrict__ bh,
                  float* out) {
    extern __shared__ __align__(16) char smc[];
    const uint32_t smb = smem_u32(smc);
    const int tid  = threadIdx.x;
    const int lane = tid & 31;
    const int warp = tid >> 5;
    uint32_t rank;
    asm("mov.u32 %0, %%cluster_ctarank;" : "=r"(rank));
    const int b0 = (blockIdx.x >> 1) * 16;       // batch base
    const int nh = rank * 128;                   // owned n-half base

    // ---- load Wh half (hi/lo) into smem, row stride 264 bf16 (=528 B)
    #pragma unroll
    for (int it = 0; it < 16; it++) {
        int u = tid + 256 * it;                  // 4096 uint4 total
        int n = u >> 5, kk = u & 31;
        uint32_t off = (uint32_t)(n * 528 + kk * 16);
        *(uint4*)(smc + S_WHH + off) = ((const uint4*)g_WhH)[(size_t)(nh + n) * 32 + kk];
        *(uint4*)(smc + S_WHL + off) = ((const uint4*)g_WhL)[(size_t)(nh + n) * 32 + kk];
    }
    // ---- init h buffer 0 with full h0 (both halves), bf16 hi/lo split
    for (int idx = tid; idx < 16 * 264; idx += 256) {
        int m = idx / 264, c = idx - m * 264;
        float v = (c < Hn) ? h0[(size_t)(b0 + m) * Hn + c] : 0.0f;
        uint32_t bv = __float_as_uint(v);
        *(unsigned short*)(smc + S_HB + m * 528 + c * 2) = (unsigned short)(bv >> 16);
        float r = v - __uint_as_float(bv & 0xFFFF0000u);
        *(unsigned short*)(smc + S_HB + HB_LO + m * 528 + c * 2) =
            __bfloat16_as_ushort(__float2bfloat16(r));
    }
    __syncthreads();

    // ---- Wh fragments -> registers (persistent across all steps)
    uint32_t bhf[16][4], blf[16][4];
    const uint32_t boff = (uint32_t)((16 * warp + ((lane >> 4) << 3) + (lane & 7)) * 528 +
                                     ((lane >> 3) & 1) * 16);
    #pragma unroll
    for (int ks = 0; ks < 16; ks++) {
        ldsm4(bhf[ks], smb + S_WHH + boff + ks * 32);
        ldsm4(blf[ks], smb + S_WHL + boff + ks * 32);
    }

    // ---- geometry + bias
    const int g = lane >> 2, tg = lane & 3;
    const int colA = nh + 16 * warp + 2 * tg;    // always < 250
    const int colB = colA + 8;                   // may exceed 249 (rank 1, warp 7)
    const float2 biasA = *(const float2*)(bh + colA);
    const float2 biasB = (colB < Hn) ? *(const float2*)(bh + colB) : make_float2(0.f, 0.f);
    const uint32_t aoffs = (uint32_t)((lane & 15) * 528 + (lane >> 4) * 16);

    uint32_t peer_hb;
    asm("mapa.shared::cluster.u32 %0, %1, %2;"
        : "=r"(peer_hb) : "r"(smb + S_HB), "r"(rank ^ 1));

    // preload xp for t = 0 (subsequent steps prefetch in the prior epilogue)
    float2 xpA0, xpA8, xpB0, xpB8;
    {
        const size_t o0 = (size_t)(b0 + g) * Tn * Hn;
        const size_t o8 = (size_t)(b0 + g + 8) * Tn * Hn;
        xpA0 = *(const float2*)(out + o0 + colA);
        xpA8 = *(const float2*)(out + o8 + colA);
        xpB0 = (colB < Hn) ? *(const float2*)(out + o0 + colB) : make_float2(0.f, 0.f);
        xpB8 = (colB < Hn) ? *(const float2*)(out + o8 + colB) : make_float2(0.f, 0.f);
    }

    for (int t = 0; t < Tn; t++) {
        if (t > 0) CLUSTER_WAIT();               // peer's step-(t-1) h delivered

        const uint32_t hbR = smb + S_HB + (uint32_t)(t & 1) * HB_SZ;

        float acc0[4] = {0.f, 0.f, 0.f, 0.f};
        float acc1[4] = {0.f, 0.f, 0.f, 0.f};

        #pragma unroll
        for (int ks = 0; ks < 16; ks++) {
            uint32_t ah[4], al[4];
            ldsm4(ah, hbR + aoffs + ks * 32);
            ldsm4(al, hbR + HB_LO + aoffs + ks * 32);
            mma16816(acc0, ah, bhf[ks]);
            mma16816(acc1, ah, bhf[ks] + 2);
            mma16816(acc0, ah, blf[ks]);
            mma16816(acc1, ah, blf[ks] + 2);
            mma16816(acc0, al, bhf[ks]);
            mma16816(acc1, al, bhf[ks] + 2);
        }

        // ---- prefetch xp(t+1) NOW: latency hides behind epilogue + barrier
        const size_t orow0 = ((size_t)(b0 + g) * Tn + t) * Hn;
        const size_t orow8 = ((size_t)(b0 + g + 8) * Tn + t) * Hn;
        float2 nxA0, nxA8, nxB0, nxB8;
        bool havenx = (t + 1 < Tn);
        if (havenx) {
            nxA0 = *(const float2*)(out + orow0 + Hn + colA);
            nxA8 = *(const float2*)(out + orow8 + Hn + colA);
            if (colB < Hn) {
                nxB0 = *(const float2*)(out + orow0 + Hn + colB);
                nxB8 = *(const float2*)(out + orow8 + Hn + colB);
            }
        }

        // ---- epilogue: tanh, write out, split h -> own + peer next buffer
        const uint32_t hbW  = smb + S_HB + (uint32_t)((t + 1) & 1) * HB_SZ;
        const uint32_t phbW = peer_hb + (uint32_t)((t + 1) & 1) * HB_SZ;

        float vA0 = tanh_fast(acc0[0] + xpA0.x + biasA.x);
        float vA1 = tanh_fast(acc0[1] + xpA0.y + biasA.y);
        float vA2 = tanh_fast(acc0[2] + xpA8.x + biasA.x);
        float vA3 = tanh_fast(acc0[3] + xpA8.y + biasA.y);
        *(float2*)(out + orow0 + colA) = make_float2(vA0, vA1);
        *(float2*)(out + orow8 + colA) = make_float2(vA2, vA3);

        float vB0 = 0.f, vB1 = 0.f, vB2 = 0.f, vB3 = 0.f;
        if (colB < Hn) {
            vB0 = tanh_fast(acc1[0] + xpB0.x + biasB.x);
            vB1 = tanh_fast(acc1[1] + xpB0.y + biasB.y);
            vB2 = tanh_fast(acc1[2] + xpB8.x + biasB.x);
            vB3 = tanh_fast(acc1[3] + xpB8.y + biasB.y);
            *(float2*)(out + orow0 + colB) = make_float2(vB0, vB1);
            *(float2*)(out + orow8 + colB) = make_float2(vB2, vB3);
        }

        #define STORE_H(row, col, v0, v1) do {                                   \
            uint32_t hp = __byte_perm(__float_as_uint(v0), __float_as_uint(v1),  \
                                      0x7632);                                   \
            float r0_ = (v0) - __uint_as_float(__float_as_uint(v0) & 0xFFFF0000u);\
            float r1_ = (v1) - __uint_as_float(__float_as_uint(v1) & 0xFFFF0000u);\
            uint32_t lp = bf16x2_rn(r0_, r1_);                                   \
            uint32_t off_ = (uint32_t)((row) * 528 + (col) * 2);                 \
            sts_u32(hbW + off_, hp);                                             \
            sts_u32(hbW + HB_LO + off_, lp);                                     \
            sts_cluster_u32(phbW + off_, hp);                                    \
            sts_cluster_u32(phbW + HB_LO + off_, lp);                            \
        } while (0)

        STORE_H(g,     colA, vA0, vA1);
        STORE_H(g + 8, colA, vA2, vA3);
        STORE_H(g,     colB, vB0, vB1);
        STORE_H(g + 8, colB, vB2, vB3);
        #undef STORE_H

        // rotate prefetched xp into place
        if (havenx) {
            xpA0 = nxA0; xpA8 = nxA8;
            if (colB < Hn) { xpB0 = nxB0; xpB8 = nxB8; }
        }

        __syncthreads();
        CLUSTER_ARRIVE();
    }
    CLUSTER_WAIT();   // balance final arrive; no CTA exits while peer may store
}

// ---------------- launch ------------------------------------------------------
extern "C" void kernel_launch(void* const* d_in, const int* in_sizes, int n_in,
                              void* d_out, int out_size) {
    const float* x  = (const float*)d_in[0];   // [512,512,256]
    const float* h0 = (const float*)d_in[1];   // [512,250]
    const float* Wx = (const float*)d_in[2];   // [250,256]
    const float* Wh = (const float*)d_in[3];   // [250,250]
    const float* bh = (const float*)d_in[4];   // [250]
    float* out = (float*)d_out;                // [512,512,250]

    // 1) weight + input prep
    prep_wx_kernel<<<256, 256>>>(Wx);
    prep_wh_kernel<<<256, 256>>>(Wh);
    prep_x_kernel<<<((size_t)Bn * Tn * In / 4) / 256, 256>>>(x);

    // 2) xproj HMMA GEMM (R8 shape: occ 2, grid.y = 2)
    cudaFuncSetAttribute(gemm_xproj_hmma,
                         cudaFuncAttributeMaxDynamicSharedMemorySize, SMTOT);
    dim3 grid((Bn * Tn) / 128, 2);
    gemm_xproj_hmma<<<grid, 256, SMTOT>>>(out);

    // 3) HMMA recurrent scan (clustered, in-place over d_out)
    cudaFuncSetAttribute(rnn_scan_mma,
                         cudaFuncAttributeMaxDynamicSharedMemorySize, S_TOT);
    rnn_scan_mma<<<Bn / 8, 256, S_TOT>>>(h0, bh, out);
}

// round 13
// speedup vs baseline: 1.7100x; 1.1470x over previous
#include <cuda_runtime.h>
#include <cuda_bf16.h>
#include <math.h>
#include <stdint.h>

// Problem dims
#define Bn 512
#define Tn 512
#define In 256
#define Hn 250

// ---------------- helpers ----------------------------------------------------
__device__ __forceinline__ uint32_t smem_u32(const void* p) {
    uint32_t a;
    asm("{ .reg .u64 t; cvta.to.shared.u64 t, %1; cvt.u32.u64 %0, t; }"
        : "=r"(a) : "l"(p));
    return a;
}
__device__ __forceinline__ uint32_t bf16x2_rn(float lo, float hi) {
    uint32_t r;
    asm("cvt.rn.bf16x2.f32 %0, %1, %2;" : "=r"(r) : "f"(hi), "f"(lo));
    return r;
}
__device__ __forceinline__ void ldsm4(uint32_t* r, uint32_t addr) {
    asm volatile("ldmatrix.sync.aligned.m8n8.x4.shared.b16 {%0,%1,%2,%3}, [%4];"
                 : "=r"(r[0]), "=r"(r[1]), "=r"(r[2]), "=r"(r[3]) : "r"(addr));
}
__device__ __forceinline__ void ldsm2(uint32_t* r, uint32_t addr) {
    asm volatile("ldmatrix.sync.aligned.m8n8.x2.shared.b16 {%0,%1}, [%2];"
                 : "=r"(r[0]), "=r"(r[1]) : "r"(addr));
}
__device__ __forceinline__ void mma16816(float* c, const uint32_t* a,
                                         const uint32_t* b) {
    asm volatile(
        "mma.sync.aligned.m16n8k16.row.col.f32.bf16.bf16.f32 "
        "{%0,%1,%2,%3}, {%4,%5,%6,%7}, {%8,%9}, {%0,%1,%2,%3};"
        : "+f"(c[0]), "+f"(c[1]), "+f"(c[2]), "+f"(c[3])
        : "r"(a[0]), "r"(a[1]), "r"(a[2]), "r"(a[3]), "r"(b[0]), "r"(b[1]));
}
#define CPASYNC16(dst, src) \
    asm volatile("cp.async.cg.shared.global [%0], [%1], 16;" \
                 :: "r"(dst), "l"(src))
#define CP_COMMIT() asm volatile("cp.async.commit_group;" ::: "memory")
#define CP_WAIT1()  asm volatile("cp.async.wait_group 1;" ::: "memory")
#define CLUSTER_ARRIVE() asm volatile("barrier.cluster.arrive.aligned;" ::: "memory")
#define CLUSTER_WAIT()   asm volatile("barrier.cluster.wait.aligned;" ::: "memory")

__device__ __forceinline__ void sts_u32(uint32_t addr, uint32_t v) {
    asm volatile("st.shared.u32 [%0], %1;" :: "r"(addr), "r"(v));
}
__device__ __forceinline__ void sts_cluster_u32(uint32_t addr, uint32_t v) {
    asm volatile("st.shared::cluster.u32 [%0], %1;" :: "r"(addr), "r"(v));
}

// fast tanh: 1 - 2/(e^{2x}+1), MUFU-based (abs err ~1e-6)
__device__ __forceinline__ float tanh_fast(float x) {
    float e;
    asm("ex2.approx.f32 %0, %1;" : "=f"(e) : "f"(x * 2.8853900817779268f));
    float r;
    asm("rcp.approx.f32 %0, %1;" : "=f"(r) : "f"(e + 1.0f));
    return fmaf(-2.0f, r, 1.0f);
}

// ---------------- scratch ----------------------------------------------------
__device__ unsigned short g_WxH[256 * 256];             // Wx hi bf16 [n][k]
__device__ unsigned short g_WxL[256 * 256];             // Wx lo bf16 [n][k]
__device__ unsigned short g_WhH[256 * 256];             // Wh hi bf16 [n][k] padded
__device__ unsigned short g_WhL[256 * 256];             // Wh lo bf16 [n][k] padded
__device__ unsigned short g_XH[(size_t)Bn * Tn * In];   // x hi bf16 (128 MB)
__device__ unsigned short g_XL[(size_t)Bn * Tn * In];   // x lo bf16 (128 MB)

__global__ void prep_wx_kernel(const float* __restrict__ Wx) {
    int i = blockIdx.x * blockDim.x + threadIdx.x;   // 256*256
    int r = i >> 8;
    int k = i & 255;
    float w = (r < Hn) ? Wx[r * In + k] : 0.0f;
    uint32_t wb = __float_as_uint(w);
    float hif = __uint_as_float(wb & 0xFFFF0000u);
    g_WxH[i] = (unsigned short)(wb >> 16);
    g_WxL[i] = __bfloat16_as_ushort(__float2bfloat16(w - hif));
}

__global__ void prep_wh_kernel(const float* __restrict__ Wh) {
    int i = blockIdx.x * blockDim.x + threadIdx.x;   // 256*256
    int r = i >> 8;
    int k = i & 255;
    float w = (r < Hn && k < Hn) ? Wh[r * Hn + k] : 0.0f;
    uint32_t wb = __float_as_uint(w);
    float hif = __uint_as_float(wb & 0xFFFF0000u);
    g_WhH[i] = (unsigned short)(wb >> 16);
    g_WhL[i] = __bfloat16_as_ushort(__float2bfloat16(w - hif));
}

__global__ void prep_x_kernel(const float* __restrict__ X) {
    size_t i = (size_t)blockIdx.x * blockDim.x + threadIdx.x;   // float4 id
    float4 v = ((const float4*)X)[i];
    uint2 hp, lp;
    hp.x = __byte_perm(__float_as_uint(v.x), __float_as_uint(v.y), 0x7632);
    hp.y = __byte_perm(__float_as_uint(v.z), __float_as_uint(v.w), 0x7632);
    #define REM(f) ((f) - __uint_as_float(__float_as_uint(f) & 0xFFFF0000u))
    lp.x = bf16x2_rn(REM(v.x), REM(v.y));
    lp.y = bf16x2_rn(REM(v.z), REM(v.w));
    #undef REM
    ((uint2*)g_XH)[i] = hp;
    ((uint2*)g_XL)[i] = lp;
}

// ---------------- Phase 1: xproj via HMMA bf16-split GEMM (R8 proven) --------
#define SBH   80
#define RBUF  (128 * SBH)
#define STG   (4 * RBUF)
#define SMTOT (2 * STG)

__global__ __launch_bounds__(256, 2)
void gemm_xproj_hmma(float* __restrict__ out) {
    extern __shared__ __align__(16) char smc[];
    const uint32_t smb = smem_u32(smc);

    const int tid  = threadIdx.x;
    const int lane = tid & 31;
    const int warp = tid >> 5;
    const int wm = warp >> 1;
    const int wn = warp & 1;
    const size_t m0 = (size_t)blockIdx.x * 128;
    const int n0c = blockIdx.y * 128;

    const int r0 = tid >> 1, c40 = (tid & 1) * 2;
    const char* gxh = (const char*)g_XH;
    const char* gxl = (const char*)g_XL;
    const char* gwh = (const char*)g_WxH;
    const char* gwl = (const char*)g_WxL;

    float acc[2][8][4];
    #pragma unroll
    for (int mi = 0; mi < 2; mi++)
        #pragma unroll
        for (int ni = 0; ni < 8; ni++)
            #pragma unroll
            for (int q = 0; q < 4; q++) acc[mi][ni][q] = 0.0f;

    const uint32_t aoff = (uint32_t)((wm * 32 + (lane & 15)) * SBH + (lane >> 4) * 16);
    const uint32_t boff = (uint32_t)((wn * 64 + (lane >> 4) * 8 + (lane & 7)) * SBH +
                                     ((lane >> 3) & 1) * 16);

    auto load_stage = [&](int s, int k0) {
        uint32_t sb = smb + s * STG;
        #pragma unroll
        for (int i = 0; i < 2; i++) {
            int c4 = c40 + i;
            uint32_t d = sb + r0 * SBH + c4 * 16;
            size_t ao = ((m0 + r0) * In + k0 + c4 * 8) * 2;
            size_t bo = (((size_t)(n0c + r0)) * In + k0 + c4 * 8) * 2;
            CPASYNC16(d,            gxh + ao);
            CPASYNC16(d + RBUF,     gxl + ao);
            CPASYNC16(d + 2 * RBUF, gwh + bo);
            CPASYNC16(d + 3 * RBUF, gwl + bo);
        }
    };

    load_stage(0, 0);  CP_COMMIT();
    load_stage(1, 32); CP_COMMIT();

    for (int c = 0; c < 8; c++) {
        CP_WAIT1();
        __syncthreads();

        const uint32_t sb = smb + (c & 1) * STG;
        const uint32_t a_h = sb + aoff,            a_l = sb + RBUF + aoff;
        const uint32_t b_h = sb + 2 * RBUF + boff, b_l = sb + 3 * RBUF + boff;

        #pragma unroll
        for (int ks = 0; ks < 2; ks++) {
            const uint32_t ko = ks * 32;
            uint32_t ahf[2][4], alf[2][4], bf[8][2];
            ldsm4(ahf[0], a_h + ko);
            ldsm4(ahf[1], a_h + 16 * SBH + ko);
            ldsm4(alf[0], a_l + ko);
            ldsm4(alf[1], a_l + 16 * SBH + ko);
            #pragma unroll
            for (int jp = 0; jp < 4; jp++) {
                uint32_t r[4];
                ldsm4(r, b_h + jp * 16 * SBH + ko);
                bf[jp * 2][0] = r[0]; bf[jp * 2][1] = r[1];
                bf[jp * 2 + 1][0] = r[2]; bf[jp * 2 + 1][1] = r[3];
            }
            #pragma unroll
            for (int mi = 0; mi < 2; mi++)
                #pragma unroll
                for (int ni = 0; ni < 8; ni++) {
                    mma16816(acc[mi][ni], ahf[mi], bf[ni]);
                    mma16816(acc[mi][ni], alf[mi], bf[ni]);
                }
            #pragma unroll
            for (int jp = 0; jp < 4; jp++) {
                uint32_t r[4];
                ldsm4(r, b_l + jp * 16 * SBH + ko);
                bf[jp * 2][0] = r[0]; bf[jp * 2][1] = r[1];
                bf[jp * 2 + 1][0] = r[2]; bf[jp * 2 + 1][1] = r[3];
            }
            #pragma unroll
            for (int mi = 0; mi < 2; mi++)
                #pragma unroll
                for (int ni = 0; ni < 8; ni++)
                    mma16816(acc[mi][ni], ahf[mi], bf[ni]);
        }
        __syncthreads();

        if (c + 2 < 8) load_stage(c & 1, (c + 2) * 32);
        CP_COMMIT();
    }

    const int g = lane >> 2, tg = lane & 3;
    #pragma unroll
    for (int mi = 0; mi < 2; mi++) {
        size_t r = m0 + wm * 32 + mi * 16 + g;
        #pragma unroll
        for (int ni = 0; ni < 8; ni++) {
            int col = n0c + wn * 64 + ni * 8 + tg * 2;
            if (col < Hn) {
                *(float2*)(out + r * Hn + col) =
                    make_float2(acc[mi][ni][0], acc[mi][ni][1]);
                *(float2*)(out + (r + 8) * Hn + col) =
                    make_float2(acc[mi][ni][2], acc[mi][ni][3]);
            }
        }
    }
}

// ---------------- Phase 2: HMMA recurrent scan (4-CTA cluster) ---------------
// 128 CTAs = 32 clusters. Cluster handles 16 batches; CTA rank owns output
// cols [64r, 64r+64). Wh quarter (bf16 hi+lo) staged in smem, its mma B
// fragments in REGISTERS for all 512 steps (64 regs). h ([16][264] bf16 hi/lo)
// ping-pongs in smem, broadcast each step to all 4 CTAs.
#define WH_SZ  (64 * 528)                   // 33792 per (hi|lo)
#define S_WHH  16
#define S_WHL  (S_WHH + WH_SZ)
#define S_HB   (S_WHL + WH_SZ)              // 67600
#define HB_SZ  16896                        // (hi + lo) [16][264] bf16
#define HB_LO  8448
#define S_TOT  (S_HB + 2 * HB_SZ)           // 101392 B

__global__ __launch_bounds__(256, 1) __cluster_dims__(4, 1, 1)
void rnn_scan_mma(const float* __restrict__ h0,
                  const float* __restrict__ bh,
                  float* out) {
    extern __shared__ __align__(16) char smc[];
    const uint32_t smb = smem_u32(smc);
    const int tid  = threadIdx.x;
    const int lane = tid & 31;
    const int warp = tid >> 5;
    uint32_t rank;
    asm("mov.u32 %0, %%cluster_ctarank;" : "=r"(rank));
    const int b0 = (blockIdx.x >> 2) * 16;       // batch base
    const int nh = rank * 64;                    // owned n-quarter base

    // ---- load Wh quarter (hi/lo) into smem, row stride 528 B
    #pragma unroll
    for (int it = 0; it < 8; it++) {
        int u = tid + 256 * it;                  // 2048 uint4 total
        int n = u >> 5, kk = u & 31;
        uint32_t off = (uint32_t)(n * 528 + kk * 16);
        *(uint4*)(smc + S_WHH + off) = ((const uint4*)g_WhH)[(size_t)(nh + n) * 32 + kk];
        *(uint4*)(smc + S_WHL + off) = ((const uint4*)g_WhL)[(size_t)(nh + n) * 32 + kk];
    }
    // ---- init h buffer 0 with full h0 (hi/lo split); pads (c>=250) zero
    for (int idx = tid; idx < 16 * 264; idx += 256) {
        int m = idx / 264, c = idx - m * 264;
        float v = (c < Hn) ? h0[(size_t)(b0 + m) * Hn + c] : 0.0f;
        uint32_t bv = __float_as_uint(v);
        *(unsigned short*)(smc + S_HB + m * 528 + c * 2) = (unsigned short)(bv >> 16);
        float r = v - __uint_as_float(bv & 0xFFFF0000u);
        *(unsigned short*)(smc + S_HB + HB_LO + m * 528 + c * 2) =
            __bfloat16_as_ushort(__float2bfloat16(r));
    }
    // ---- zero buffer1 pad cols 250..263 (never stored later; must be finite)
    for (int idx = tid; idx < 16 * 14; idx += 256) {
        int m = idx / 14, c = 250 + (idx % 14);
        *(unsigned short*)(smc + S_HB + HB_SZ + m * 528 + c * 2) = 0;
        *(unsigned short*)(smc + S_HB + HB_SZ + HB_LO + m * 528 + c * 2) = 0;
    }
    __syncthreads();
    // all CTAs finish init before any remote store can land
    CLUSTER_ARRIVE();
    CLUSTER_WAIT();

    // ---- Wh B fragments -> registers (persistent; one n8-tile per warp)
    uint32_t bhf[16][2], blf[16][2];
    const uint32_t bwoff = (uint32_t)((8 * warp + (lane & 7)) * 528 +
                                      ((lane >> 3) & 1) * 16);
    #pragma unroll
    for (int ks = 0; ks < 16; ks++) {
        ldsm2(bhf[ks], smb + S_WHH + bwoff + ks * 32);
        ldsm2(blf[ks], smb + S_WHL + bwoff + ks * 32);
    }

    // ---- geometry + bias
    const int g = lane >> 2, tg = lane & 3;
    const int colA = nh + 8 * warp + 2 * tg;     // even; 248 valid, >=250 pad
    const bool colok = (colA < Hn);
    const float2 biasA = colok ? *(const float2*)(bh + colA) : make_float2(0.f, 0.f);
    const uint32_t aoffs = (uint32_t)((lane & 15) * 528 + (lane >> 4) * 16);

    // peer h-buffer bases (3 peers)
    uint32_t phb[3];
    #pragma unroll
    for (int d = 0; d < 3; d++) {
        uint32_t pr = (rank + 1 + d) & 3;
        asm("mapa.shared::cluster.u32 %0, %1, %2;"
            : "=r"(phb[d]) : "r"(smb + S_HB), "r"(pr));
    }

    // preload xp for t = 0
    float2 xpA0, xpA8;
    {
        const size_t o0 = (size_t)(b0 + g) * Tn * Hn;
        const size_t o8 = (size_t)(b0 + g + 8) * Tn * Hn;
        xpA0 = colok ? *(const float2*)(out + o0 + colA) : make_float2(0.f, 0.f);
        xpA8 = colok ? *(const float2*)(out + o8 + colA) : make_float2(0.f, 0.f);
    }

    for (int t = 0; t < Tn; t++) {
        if (t > 0) CLUSTER_WAIT();               // all peers' step-(t-1) h here

        const uint32_t hbR = smb + S_HB + (uint32_t)(t & 1) * HB_SZ;

        // 3 accumulators -> dependency chains of 16 mma each
        float accP[4] = {0.f, 0.f, 0.f, 0.f};
        float accQ[4] = {0.f, 0.f, 0.f, 0.f};
        float accR[4] = {0.f, 0.f, 0.f, 0.f};

        #pragma unroll
        for (int ks = 0; ks < 16; ks++) {
            uint32_t ah[4], al[4];
            ldsm4(ah, hbR + aoffs + ks * 32);
            ldsm4(al, hbR + HB_LO + aoffs + ks * 32);
            mma16816(accP, ah, bhf[ks]);
            mma16816(accQ, ah, blf[ks]);
            mma16816(accR, al, bhf[ks]);
        }

        // prefetch xp(t+1): hides behind epilogue + barrier
        const size_t orow0 = ((size_t)(b0 + g) * Tn + t) * Hn;
        const size_t orow8 = ((size_t)(b0 + g + 8) * Tn + t) * Hn;
        float2 nxA0, nxA8;
        const bool havenx = (t + 1 < Tn) && colok;
        if (havenx) {
            nxA0 = *(const float2*)(out + orow0 + Hn + colA);
            nxA8 = *(const float2*)(out + orow8 + Hn + colA);
        }

        // ---- epilogue
        const uint32_t hbW  = smb + S_HB + (uint32_t)((t + 1) & 1) * HB_SZ;
        const uint32_t pb   = (uint32_t)((t + 1) & 1) * HB_SZ;

        if (colok) {
            float v0 = tanh_fast(accP[0] + accQ[0] + accR[0] + xpA0.x + biasA.x);
            float v1 = tanh_fast(accP[1] + accQ[1] + accR[1] + xpA0.y + biasA.y);
            float v2 = tanh_fast(accP[2] + accQ[2] + accR[2] + xpA8.x + biasA.x);
            float v3 = tanh_fast(accP[3] + accQ[3] + accR[3] + xpA8.y + biasA.y);
            *(float2*)(out + orow0 + colA) = make_float2(v0, v1);
            *(float2*)(out + orow8 + colA) = make_float2(v2, v3);

            #define STORE_H(row, v0_, v1_) do {                                  \
                uint32_t hp = __byte_perm(__float_as_uint(v0_),                  \
                                          __float_as_uint(v1_), 0x7632);         \
                float r0_ = (v0_) - __uint_as_float(__float_as_uint(v0_) & 0xFFFF0000u); \
                float r1_ = (v1_) - __uint_as_float(__float_as_uint(v1_) & 0xFFFF0000u); \
                uint32_t lp = bf16x2_rn(r0_, r1_);                               \
                uint32_t off_ = (uint32_t)((row) * 528 + colA * 2);              \
                sts_u32(hbW + off_, hp);                                         \
                sts_u32(hbW + HB_LO + off_, lp);                                 \
                sts_cluster_u32(phb[0] + pb + off_, hp);                         \
                sts_cluster_u32(phb[0] + pb + HB_LO + off_, lp);                 \
                sts_cluster_u32(phb[1] + pb + off_, hp);                         \
                sts_cluster_u32(phb[1] + pb + HB_LO + off_, lp);                 \
                sts_cluster_u32(phb[2] + pb + off_, hp);                         \
                sts_cluster_u32(phb[2] + pb + HB_LO + off_, lp);                 \
            } while (0)

            STORE_H(g,     v0, v1);
            STORE_H(g + 8, v2, v3);
            #undef STORE_H
        }

        if (havenx) { xpA0 = nxA0; xpA8 = nxA8; }

        __syncthreads();
        CLUSTER_ARRIVE();
    }
    CLUSTER_WAIT();   // balance final arrive; no CTA exits early
}

// ---------------- launch ------------------------------------------------------
extern "C" void kernel_launch(void* const* d_in, const int* in_sizes, int n_in,
                              void* d_out, int out_size) {
    const float* x  = (const float*)d_in[0];   // [512,512,256]
    const float* h0 = (const float*)d_in[1];   // [512,250]
    const float* Wx = (const float*)d_in[2];   // [250,256]
    const float* Wh = (const float*)d_in[3];   // [250,250]
    const float* bh = (const float*)d_in[4];   // [250]
    float* out = (float*)d_out;                // [512,512,250]

    // 1) weight + input prep
    prep_wx_kernel<<<256, 256>>>(Wx);
    prep_wh_kernel<<<256, 256>>>(Wh);
    prep_x_kernel<<<((size_t)Bn * Tn * In / 4) / 256, 256>>>(x);

    // 2) xproj HMMA GEMM (R8 shape: occ 2, grid.y = 2)
    cudaFuncSetAttribute(gemm_xproj_hmma,
                         cudaFuncAttributeMaxDynamicSharedMemorySize, SMTOT);
    dim3 grid((Bn * Tn) / 128, 2);
    gemm_xproj_hmma<<<grid, 256, SMTOT>>>(out);

    // 3) HMMA recurrent scan (4-CTA clusters, in-place over d_out)
    cudaFuncSetAttribute(rnn_scan_mma,
                         cudaFuncAttributeMaxDynamicSharedMemorySize, S_TOT);
    rnn_scan_mma<<<(Bn / 16) * 4, 256, S_TOT>>>(h0, bh, out);
}

// round 15
// speedup vs baseline: 1.7943x; 1.0493x over previous
#include <cuda_runtime.h>
#include <cuda_bf16.h>
#include <math.h>
#include <stdint.h>

// Problem dims
#define Bn 512
#define Tn 512
#define In 256
#define Hn 250

// ---------------- helpers ----------------------------------------------------
__device__ __forceinline__ uint32_t smem_u32(const void* p) {
    uint32_t a;
    asm("{ .reg .u64 t; cvta.to.shared.u64 t, %1; cvt.u32.u64 %0, t; }"
        : "=r"(a) : "l"(p));
    return a;
}
__device__ __forceinline__ uint32_t bf16x2_rn(float lo, float hi) {
    uint32_t r;
    asm("cvt.rn.bf16x2.f32 %0, %1, %2;" : "=r"(r) : "f"(hi), "f"(lo));
    return r;
}
__device__ __forceinline__ void ldsm4(uint32_t* r, uint32_t addr) {
    asm volatile("ldmatrix.sync.aligned.m8n8.x4.shared.b16 {%0,%1,%2,%3}, [%4];"
                 : "=r"(r[0]), "=r"(r[1]), "=r"(r[2]), "=r"(r[3]) : "r"(addr));
}
__device__ __forceinline__ void ldsm2(uint32_t* r, uint32_t addr) {
    asm volatile("ldmatrix.sync.aligned.m8n8.x2.shared.b16 {%0,%1}, [%2];"
                 : "=r"(r[0]), "=r"(r[1]) : "r"(addr));
}
__device__ __forceinline__ void mma16816(float* c, const uint32_t* a,
                                         const uint32_t* b) {
    asm volatile(
        "mma.sync.aligned.m16n8k16.row.col.f32.bf16.bf16.f32 "
        "{%0,%1,%2,%3}, {%4,%5,%6,%7}, {%8,%9}, {%0,%1,%2,%3};"
        : "+f"(c[0]), "+f"(c[1]), "+f"(c[2]), "+f"(c[3])
        : "r"(a[0]), "r"(a[1]), "r"(a[2]), "r"(a[3]), "r"(b[0]), "r"(b[1]));
}
#define CPASYNC16(dst, src) \
    asm volatile("cp.async.cg.shared.global [%0], [%1], 16;" \
                 :: "r"(dst), "l"(src))
#define CP_COMMIT() asm volatile("cp.async.commit_group;" ::: "memory")
#define CP_WAIT1()  asm volatile("cp.async.wait_group 1;" ::: "memory")
#define CLUSTER_ARRIVE() asm volatile("barrier.cluster.arrive.aligned;" ::: "memory")
#define CLUSTER_WAIT()   asm volatile("barrier.cluster.wait.aligned;" ::: "memory")

__device__ __forceinline__ void sts_u32(uint32_t addr, uint32_t v) {
    asm volatile("st.shared.u32 [%0], %1;" :: "r"(addr), "r"(v));
}
__device__ __forceinline__ void sts_cluster_u32(uint32_t addr, uint32_t v) {
    asm volatile("st.shared::cluster.u32 [%0], %1;" :: "r"(addr), "r"(v));
}

// fast tanh: 1 - 2/(e^{2x}+1), MUFU-based (abs err ~1e-6)
__device__ __forceinline__ float tanh_fast(float x) {
    float e;
    asm("ex2.approx.f32 %0, %1;" : "=f"(e) : "f"(x * 2.8853900817779268f));
    float r;
    asm("rcp.approx.f32 %0, %1;" : "=f"(r) : "f"(e + 1.0f));
    return fmaf(-2.0f, r, 1.0f);
}

// hi = truncation to bf16 (upper 16 bits), identical math to prior prep_x
#define FHI(f) __uint_as_float(__float_as_uint(f) & 0xFFFF0000u)
#define FREM(f) ((f) - FHI(f))

// ---------------- scratch ----------------------------------------------------
__device__ unsigned short g_WxH[256 * 256];             // Wx hi bf16 [n][k]
__device__ unsigned short g_WxL[256 * 256];             // Wx lo bf16 [n][k]
__device__ unsigned short g_WhH[256 * 256];             // Wh hi bf16 [n][k] padded
__device__ unsigned short g_WhL[256 * 256];             // Wh lo bf16 [n][k] padded

__global__ void prep_wx_kernel(const float* __restrict__ Wx) {
    int i = blockIdx.x * blockDim.x + threadIdx.x;   // 256*256
    int r = i >> 8;
    int k = i & 255;
    float w = (r < Hn) ? Wx[r * In + k] : 0.0f;
    g_WxH[i] = (unsigned short)(__float_as_uint(w) >> 16);
    g_WxL[i] = __bfloat16_as_ushort(__float2bfloat16(FREM(w)));
}

__global__ void prep_wh_kernel(const float* __restrict__ Wh) {
    int i = blockIdx.x * blockDim.x + threadIdx.x;   // 256*256
    int r = i >> 8;
    int k = i & 255;
    float w = (r < Hn && k < Hn) ? Wh[r * Hn + k] : 0.0f;
    g_WhH[i] = (unsigned short)(__float_as_uint(w) >> 16);
    g_WhL[i] = __bfloat16_as_ushort(__float2bfloat16(FREM(w)));
}

// ---------------- Phase 1: xproj via HMMA bf16-split GEMM (v4) ---------------
// A staged as RAW fp32 (same bytes as hi+lo bf16); hi/lo fragments built in
// registers -> prep_x kernel eliminated. B path identical to R8.
#define A_STR  160                  // A row stride bytes (40 fp32, 16B aligned)
#define A_SZ   (128 * A_STR)        // 20480 B
#define SBH    80                   // B row stride bytes
#define RBUF_B (128 * SBH)          // 10240 B
#define STG    (A_SZ + 2 * RBUF_B)  // 40960 B
#define SMTOT  (2 * STG)            // 81920 B

__global__ __launch_bounds__(256, 2)
void gemm_xproj_hmma(const float* __restrict__ X, float* __restrict__ out) {
    extern __shared__ __align__(16) char smc[];
    const uint32_t smb = smem_u32(smc);

    const int tid  = threadIdx.x;
    const int lane = tid & 31;
    const int warp = tid >> 5;
    const int wm = warp >> 1;
    const int wn = warp & 1;
    const size_t m0 = (size_t)blockIdx.x * 128;
    const int n0c = blockIdx.y * 128;

    const int r0 = tid >> 1;
    const int ah2 = tid & 1;             // A 64B half
    const int c40 = (tid & 1) * 2;       // B chunk base
    const char* gwh = (const char*)g_WxH;
    const char* gwl = (const char*)g_WxL;

    float acc[2][8][4];
    #pragma unroll
    for (int mi = 0; mi < 2; mi++)
        #pragma unroll
        for (int ni = 0; ni < 8; ni++)
            #pragma unroll
            for (int q = 0; q < 4; q++) acc[mi][ni][q] = 0.0f;

    const int g = lane >> 2, tg = lane & 3;
    const uint32_t boff = (uint32_t)((wn * 64 + (lane >> 4) * 8 + (lane & 7)) * SBH +
                                     ((lane >> 3) & 1) * 16);

    auto load_stage = [&](int s, int k0) {
        uint32_t sb = smb + s * STG;
        // A: raw fp32, 4 chunks of 16B per thread
        {
            uint32_t d = sb + r0 * A_STR + ah2 * 64;
            const char* src = (const char*)(X + (m0 + r0) * In + k0 + ah2 * 16);
            #pragma unroll
            for (int i = 0; i < 4; i++)
                CPASYNC16(d + i * 16, src + i * 16);
        }
        // B: pre-split bf16 hi/lo, 2 chunks each
        #pragma unroll
        for (int i = 0; i < 2; i++) {
            int c4 = c40 + i;
            uint32_t d = sb + A_SZ + r0 * SBH + c4 * 16;
            size_t bo = (((size_t)(n0c + r0)) * In + k0 + c4 * 8) * 2;
            CPASYNC16(d,          gwh + bo);
            CPASYNC16(d + RBUF_B, gwl + bo);
        }
    };

    load_stage(0, 0);  CP_COMMIT();
    load_stage(1, 32); CP_COMMIT();

    for (int c = 0; c < 8; c++) {
        CP_WAIT1();
        __syncthreads();

        const char* sA = smc + (c & 1) * STG;
        const uint32_t sb = smb + (c & 1) * STG;
        const uint32_t b_h = sb + A_SZ + boff;
        const uint32_t b_l = sb + A_SZ + RBUF_B + boff;

        #pragma unroll
        for (int ks = 0; ks < 2; ks++) {
            const uint32_t ko = ks * 32;
            // ---- build A hi/lo fragments from fp32 smem (bit-identical split)
            uint32_t ahf[2][4], alf[2][4];
            #pragma unroll
            for (int mi = 0; mi < 2; mi++) {
                const int r1 = wm * 32 + mi * 16 + g;
                const float* rowp = (const float*)(sA + r1 * A_STR) + ks * 16 + 2 * tg;
                const float* rowq = (const float*)(sA + (r1 + 8) * A_STR) + ks * 16 + 2 * tg;
                float2 p0 = *(const float2*)(rowp);       // row g,   cols c,c+1
                float2 p1 = *(const float2*)(rowq);       // row g+8
                float2 p2 = *(const float2*)(rowp + 8);   // row g,   cols +8
                float2 p3 = *(const float2*)(rowq + 8);   // row g+8
                ahf[mi][0] = __byte_perm(__float_as_uint(p0.x), __float_as_uint(p0.y), 0x7632);
                ahf[mi][1] = __byte_perm(__float_as_uint(p1.x), __float_as_uint(p1.y), 0x7632);
                ahf[mi][2] = __byte_perm(__float_as_uint(p2.x), __float_as_uint(p2.y), 0x7632);
                ahf[mi][3] = __byte_perm(__float_as_uint(p3.x), __float_as_uint(p3.y), 0x7632);
                alf[mi][0] = bf16x2_rn(FREM(p0.x), FREM(p0.y));
                alf[mi][1] = bf16x2_rn(FREM(p1.x), FREM(p1.y));
                alf[mi][2] = bf16x2_rn(FREM(p2.x), FREM(p2.y));
                alf[mi][3] = bf16x2_rn(FREM(p3.x), FREM(p3.y));
            }
            uint32_t bf[8][2];
            #pragma unroll
            for (int jp = 0; jp < 4; jp++) {
                uint32_t r[4];
                ldsm4(r, b_h + jp * 16 * SBH + ko);
                bf[jp * 2][0] = r[0]; bf[jp * 2][1] = r[1];
                bf[jp * 2 + 1][0] = r[2]; bf[jp * 2 + 1][1] = r[3];
            }
            #pragma unroll
            for (int mi = 0; mi < 2; mi++)
                #pragma unroll
                for (int ni = 0; ni < 8; ni++) {
                    mma16816(acc[mi][ni], ahf[mi], bf[ni]);
                    mma16816(acc[mi][ni], alf[mi], bf[ni]);
                }
            #pragma unroll
            for (int jp = 0; jp < 4; jp++) {
                uint32_t r[4];
                ldsm4(r, b_l + jp * 16 * SBH + ko);
                bf[jp * 2][0] = r[0]; bf[jp * 2][1] = r[1];
                bf[jp * 2 + 1][0] = r[2]; bf[jp * 2 + 1][1] = r[3];
            }
            #pragma unroll
            for (int mi = 0; mi < 2; mi++)
                #pragma unroll
                for (int ni = 0; ni < 8; ni++)
                    mma16816(acc[mi][ni], ahf[mi], bf[ni]);
        }
        __syncthreads();

        if (c + 2 < 8) load_stage(c & 1, (c + 2) * 32);
        CP_COMMIT();
    }

    #pragma unroll
    for (int mi = 0; mi < 2; mi++) {
        size_t r = m0 + wm * 32 + mi * 16 + g;
        #pragma unroll
        for (int ni = 0; ni < 8; ni++) {
            int col = n0c + wn * 64 + ni * 8 + tg * 2;
            if (col < Hn) {
                *(float2*)(out + r * Hn + col) =
                    make_float2(acc[mi][ni][0], acc[mi][ni][1]);
                *(float2*)(out + (r + 8) * Hn + col) =
                    make_float2(acc[mi][ni][2], acc[mi][ni][3]);
            }
        }
    }
}

// ---------------- Phase 2: HMMA recurrent scan (4-CTA cluster, R13 proven) ---
#define WH_SZ  (64 * 528)                   // 33792 per (hi|lo)
#define S_WHH  16
#define S_WHL  (S_WHH + WH_SZ)
#define S_HB   (S_WHL + WH_SZ)              // 67600
#define HB_SZ  16896                        // (hi + lo) [16][264] bf16
#define HB_LO  8448
#define S_TOT  (S_HB + 2 * HB_SZ)           // 101392 B

__global__ __launch_bounds__(256, 1) __cluster_dims__(4, 1, 1)
void rnn_scan_mma(const float* __restrict__ h0,
                  const float* __restrict__ bh,
                  float* out) {
    extern __shared__ __align__(16) char smc[];
    const uint32_t smb = smem_u32(smc);
    const int tid  = threadIdx.x;
    const int lane = tid & 31;
    const int warp = tid >> 5;
    uint32_t rank;
    asm("mov.u32 %0, %%cluster_ctarank;" : "=r"(rank));
    const int b0 = (blockIdx.x >> 2) * 16;       // batch base
    const int nh = rank * 64;                    // owned n-quarter base

    // ---- load Wh quarter (hi/lo) into smem, row stride 528 B
    #pragma unroll
    for (int it = 0; it < 8; it++) {
        int u = tid + 256 * it;                  // 2048 uint4 total
        int n = u >> 5, kk = u & 31;
        uint32_t off = (uint32_t)(n * 528 + kk * 16);
        *(uint4*)(smc + S_WHH + off) = ((const uint4*)g_WhH)[(size_t)(nh + n) * 32 + kk];
        *(uint4*)(smc + S_WHL + off) = ((const uint4*)g_WhL)[(size_t)(nh + n) * 32 + kk];
    }
    // ---- init h buffer 0 with full h0 (hi/lo split); pads (c>=250) zero
    for (int idx = tid; idx < 16 * 264; idx += 256) {
        int m = idx / 264, c = idx - m * 264;
        float v = (c < Hn) ? h0[(size_t)(b0 + m) * Hn + c] : 0.0f;
        *(unsigned short*)(smc + S_HB + m * 528 + c * 2) =
            (unsigned short)(__float_as_uint(v) >> 16);
        *(unsigned short*)(smc + S_HB + HB_LO + m * 528 + c * 2) =
            __bfloat16_as_ushort(__float2bfloat16(FREM(v)));
    }
    // ---- zero buffer1 pad cols 250..263 (never stored later; must be finite)
    for (int idx = tid; idx < 16 * 14; idx += 256) {
        int m = idx / 14, c = 250 + (idx % 14);
        *(unsigned short*)(smc + S_HB + HB_SZ + m * 528 + c * 2) = 0;
        *(unsigned short*)(smc + S_HB + HB_SZ + HB_LO + m * 528 + c * 2) = 0;
    }
    __syncthreads();
    // all CTAs finish init before any remote store can land
    CLUSTER_ARRIVE();
    CLUSTER_WAIT();

    // ---- Wh B fragments -> registers (persistent; one n8-tile per warp)
    uint32_t bhf[16][2], blf[16][2];
    const uint32_t bwoff = (uint32_t)((8 * warp + (lane & 7)) * 528 +
                                      ((lane >> 3) & 1) * 16);
    #pragma unroll
    for (int ks = 0; ks < 16; ks++) {
        ldsm2(bhf[ks], smb + S_WHH + bwoff + ks * 32);
        ldsm2(blf[ks], smb + S_WHL + bwoff + ks * 32);
    }

    // ---- geometry + bias
    const int g = lane >> 2, tg = lane & 3;
    const int colA = nh + 8 * warp + 2 * tg;     // even; 248 valid, >=250 pad
    const bool colok = (colA < Hn);
    const float2 biasA = colok ? *(const float2*)(bh + colA) : make_float2(0.f, 0.f);
    const uint32_t aoffs = (uint32_t)((lane & 15) * 528 + (lane >> 4) * 16);

    // peer h-buffer bases (3 peers)
    uint32_t phb[3];
    #pragma unroll
    for (int d = 0; d < 3; d++) {
        uint32_t pr = (rank + 1 + d) & 3;
        asm("mapa.shared::cluster.u32 %0, %1, %2;"
            : "=r"(phb[d]) : "r"(smb + S_HB), "r"(pr));
    }

    // preload xp for t = 0
    float2 xpA0, xpA8;
    {
        const size_t o0 = (size_t)(b0 + g) * Tn * Hn;
        const size_t o8 = (size_t)(b0 + g + 8) * Tn * Hn;
        xpA0 = colok ? *(const float2*)(out + o0 + colA) : make_float2(0.f, 0.f);
        xpA8 = colok ? *(const float2*)(out + o8 + colA) : make_float2(0.f, 0.f);
    }

    for (int t = 0; t < Tn; t++) {
        if (t > 0) CLUSTER_WAIT();               // all peers' step-(t-1) h here

        const uint32_t hbR = smb + S_HB + (uint32_t)(t & 1) * HB_SZ;

        float accP[4] = {0.f, 0.f, 0.f, 0.f};
        float accQ[4] = {0.f, 0.f, 0.f, 0.f};
        float accR[4] = {0.f, 0.f, 0.f, 0.f};

        #pragma unroll
        for (int ks = 0; ks < 16; ks++) {
            uint32_t ah[4], al[4];
            ldsm4(ah, hbR + aoffs + ks * 32);
            ldsm4(al, hbR + HB_LO + aoffs + ks * 32);
            mma16816(accP, ah, bhf[ks]);
            mma16816(accQ, ah, blf[ks]);
            mma16816(accR, al, bhf[ks]);
        }

        // prefetch xp(t+1): hides behind epilogue + barrier
        const size_t orow0 = ((size_t)(b0 + g) * Tn + t) * Hn;
        const size_t orow8 = ((size_t)(b0 + g + 8) * Tn + t) * Hn;
        float2 nxA0, nxA8;
        const bool havenx = (t + 1 < Tn) && colok;
        if (havenx) {
            nxA0 = *(const float2*)(out + orow0 + Hn + colA);
            nxA8 = *(const float2*)(out + orow8 + Hn + colA);
        }

        // ---- epilogue
        const uint32_t hbW  = smb + S_HB + (uint32_t)((t + 1) & 1) * HB_SZ;
        const uint32_t pb   = (uint32_t)((t + 1) & 1) * HB_SZ;

        if (colok) {
            float v0 = tanh_fast(accP[0] + accQ[0] + accR[0] + xpA0.x + biasA.x);
            float v1 = tanh_fast(accP[1] + accQ[1] + accR[1] + xpA0.y + biasA.y);
            float v2 = tanh_fast(accP[2] + accQ[2] + accR[2] + xpA8.x + biasA.x);
            float v3 = tanh_fast(accP[3] + accQ[3] + accR[3] + xpA8.y + biasA.y);
            *(float2*)(out + orow0 + colA) = make_float2(v0, v1);
            *(float2*)(out + orow8 + colA) = make_float2(v2, v3);

            #define STORE_H(row, v0_, v1_) do {                                  \
                uint32_t hp = __byte_perm(__float_as_uint(v0_),                  \
                                          __float_as_uint(v1_), 0x7632);         \
                uint32_t lp = bf16x2_rn(FREM(v0_), FREM(v1_));                   \
                uint32_t off_ = (uint32_t)((row) * 528 + colA * 2);              \
                sts_u32(hbW + off_, hp);                                         \
                sts_u32(hbW + HB_LO + off_, lp);                                 \
                sts_cluster_u32(phb[0] + pb + off_, hp);                         \
                sts_cluster_u32(phb[0] + pb + HB_LO + off_, lp);                 \
                sts_cluster_u32(phb[1] + pb + off_, hp);                         \
                sts_cluster_u32(phb[1] + pb + HB_LO + off_, lp);                 \
                sts_cluster_u32(phb[2] + pb + off_, hp);                         \
                sts_cluster_u32(phb[2] + pb + HB_LO + off_, lp);                 \
            } while (0)

            STORE_H(g,     v0, v1);
            STORE_H(g + 8, v2, v3);
            #undef STORE_H
        }

        if (havenx) { xpA0 = nxA0; xpA8 = nxA8; }

        // cluster arrive/wait provides release/acquire for both own-CTA and
        // peer smem stores; no __syncthreads needed
        CLUSTER_ARRIVE();
    }
    CLUSTER_WAIT();   // balance final arrive; no CTA exits early
}

// ---------------- launch ------------------------------------------------------
extern "C" void kernel_launch(void* const* d_in, const int* in_sizes, int n_in,
                              void* d_out, int out_size) {
    const float* x  = (const float*)d_in[0];   // [512,512,256]
    const float* h0 = (const float*)d_in[1];   // [512,250]
    const float* Wx = (const float*)d_in[2];   // [250,256]
    const float* Wh = (const float*)d_in[3];   // [250,250]
    const float* bh = (const float*)d_in[4];   // [250]
    float* out = (float*)d_out;                // [512,512,250]

    // 1) weight prep only (x split now happens inside the GEMM)
    prep_wx_kernel<<<256, 256>>>(Wx);
    prep_wh_kernel<<<256, 256>>>(Wh);

    // 2) xproj HMMA GEMM (raw-fp32 A staging, occ 2, grid.y = 2)
    cudaFuncSetAttribute(gemm_xproj_hmma,
                         cudaFuncAttributeMaxDynamicSharedMemorySize, SMTOT);
    dim3 grid((Bn * Tn) / 128, 2);
    gemm_xproj_hmma<<<grid, 256, SMTOT>>>(x, out);

    // 3) HMMA recurrent scan (4-CTA clusters, in-place over d_out)
    cudaFuncSetAttribute(rnn_scan_mma,
                         cudaFuncAttributeMaxDynamicSharedMemorySize, S_TOT);
    rnn_scan_mma<<<(Bn / 16) * 4, 256, S_TOT>>>(h0, bh, out);
}